// round 12
// baseline (speedup 1.0000x reference)
#include <cuda_runtime.h>
#include <math.h>

#define BB 16
#define AA 3
#define SDIM 80
#define NC 80
#define NT 32
#define SSP (SDIM * SDIM)             // 6400
#define CH (5 + NC)                   // 85
#define CELLS (BB * AA * SSP)         // 307200
#define NTARG (BB * NT)               // 512 = grid size
#define NTHR 128
#define F4_TOTAL (CELLS / 4)          // 76800
#define F4_PER_BLK (F4_TOTAL / NTARG) // 150
#define EPSF 1e-7f
#define IMG 640.0f
#define STRIDEF 8.0f

__device__ __forceinline__ float softplusf(float x) {
    return fmaxf(x, 0.0f) + __logf(1.0f + __expf(-fabsf(x)));   // arg in [1,2]
}
__device__ __forceinline__ float sigmoidf(float x) {
    return 1.0f / (1.0f + __expf(-x));
}

__device__ __forceinline__ int assign_cell(float4 tb, const float* anch) {
    int gi = min(max((int)floorf(tb.x * (float)SDIM), 0), SDIM - 1);
    int gj = min(max((int)floorf(tb.y * (float)SDIM), 0), SDIM - 1);
    float tw = tb.z * IMG, th = tb.w * IMG;
    float best = -1.0f; int a = 0;
    #pragma unroll
    for (int k = 0; k < AA; k++) {
        float awk = anch[2 * k], ahk = anch[2 * k + 1];
        float inter = fminf(tw, awk) * fminf(th, ahk);
        float un = tw * th + awk * ahk - inter;
        float r = inter / un;                 // IEEE div: match jnp argmax exactly
        if (r > best) { best = r; a = k; }    // first-max wins
    }
    return (a * SDIM + gj) * SDIM + gi;
}

__device__ __forceinline__ float ciou_f(
    float px1, float py1, float px2, float py2,
    float tx1, float ty1, float tx2, float ty2)
{
    float iw = fmaxf(fminf(px2, tx2) - fmaxf(px1, tx1), 0.0f);
    float ih = fmaxf(fminf(py2, ty2) - fmaxf(py1, ty1), 0.0f);
    float inter = iw * ih;
    float pa = fmaxf(px2 - px1, 0.0f) * fmaxf(py2 - py1, 0.0f);
    float ta = fmaxf(tx2 - tx1, 0.0f) * fmaxf(ty2 - ty1, 0.0f);
    float un = pa + ta - inter + EPSF;
    float iou = inter / un;
    float dx = 0.5f * (px1 + px2) - 0.5f * (tx1 + tx2);
    float dy = 0.5f * (py1 + py2) - 0.5f * (ty1 + ty2);
    float cd = dx * dx + dy * dy;
    float ew = fmaxf(px2, tx2) - fminf(px1, tx1);
    float eh = fmaxf(py2, ty2) - fminf(py1, ty1);
    float ed = ew * ew + eh * eh + EPSF;
    float pw = fmaxf(px2 - px1, EPSF);
    float ph = fmaxf(py2 - py1, EPSF);
    float tw = fmaxf(tx2 - tx1, EPSF);
    float th = fmaxf(ty2 - ty1, EPSF);
    float da = atanf(tw / th) - atanf(pw / ph);
    float v = (4.0f / ((float)M_PI * (float)M_PI)) * da * da;
    float alpha = v / (1.0f - iou + v + EPSF);
    return iou - cd / ed - alpha * v;
}

__global__ void __launch_bounds__(NTHR)
yolo_one(const float* __restrict__ preds,
         const float* __restrict__ anchors,
         const int* __restrict__ tcls,
         const float* __restrict__ tbox,
         float* __restrict__ out)
{
    __shared__ unsigned s_bits[3];
    __shared__ float    s_objv[3];        // bce-ciou, cls_sum, sp (0 if no owner)
    __shared__ float    red_conf[4];
    __shared__ float    s_nobj[4];

    int tid  = threadIdx.x;
    int lane = tid & 31;
    int w    = tid >> 5;
    int blk  = blockIdx.x;                 // one target per block
    int b = blk >> 5, n = blk & 31;
    int w_own = b >> 2;                    // warp that handles the obj work

    float anch[2 * AA];
    #pragma unroll
    for (int k = 0; k < 2 * AA; k++) anch[k] = anchors[k];

    const float4* tbox4 = (const float4*)tbox;

    // ── RT1 (independent loads, all warps) ──
    float4 tb[4];
    #pragma unroll
    for (int r = 0; r < 4; r++)
        tb[r] = tbox4[(w * 4 + r) * NT + lane];   // warp w: batches 4w..4w+3

    // ── owner warp: dedup + RT2 issue + full obj tail (pre-barrier) ──
    if (w == w_own) {                      // warp-uniform branch
        float4 tbn = tbox4[b * NT + lane]; // batch b, one target per lane
        int    myc = tcls[b * NT + lane];

        int cell_l = assign_cell(tbn, anch);
        unsigned M  = __match_any_sync(0xffffffffu, cell_l);
        unsigned Mn = __shfl_sync(0xffffffffu, M, n);
        int   celln = __shfl_sync(0xffffffffu, cell_l, n);
        bool  owner = ((int)__ffs(Mn) - 1 == n);
        int   lastm = 31 - __clz(Mn);
        float bx = __shfl_sync(0xffffffffu, tbn.x, lastm);
        float by = __shfl_sync(0xffffffffu, tbn.y, lastm);
        float bz = __shfl_sync(0xffffffffu, tbn.z, lastm);
        float bw = __shfl_sync(0xffffffffu, tbn.w, lastm);

        int gi = celln % SDIM;
        int gj = (celln / SDIM) % SDIM;
        int a  = celln / SSP;

        if (owner) {                        // warp-uniform
            size_t base = ((size_t)b * (AA * CH) + (size_t)a * CH) * SSP
                          + (size_t)gj * SDIM + gi;
            // RT2: 85 loads as 3 predicated per lane (i = lane, +32, +64)
            // ch(i) = 5+i for classes (i<80), i-80 for box/conf (80..84)
            float v0 = 0.f, v1 = 0.f, v2 = 0.f;
            {
                int i0 = lane;
                int i1 = lane + 32;
                int i2 = lane + 64;
                v0 = preds[base + (size_t)(5 + i0) * SSP];
                v1 = preds[base + (size_t)(5 + i1) * SSP];
                if (i2 < 85) {
                    int ch = (i2 < 80) ? (5 + i2) : (i2 - 80);
                    v2 = preds[base + (size_t)ch * SSP];
                }
            }

            // class-set union while loads are in flight (owner warp only)
            if (lane < 3) s_bits[lane] = 0u;
            __syncwarp();
            if ((Mn >> lane) & 1u)
                atomicOr(&s_bits[myc >> 5], 1u << (myc & 31));
            __syncwarp();
            unsigned bb0 = s_bits[0], bb1 = s_bits[1], bb2 = s_bits[2];

            // cls BCE for i0, i1 (<80 always) and i2 when <80
            float cs = 0.f;
            {
                int i0 = lane;
                float t0 = (float)((((i0 < 32 ? bb0 : bb1) >> (i0 & 31))) & 1u);
                cs += softplusf(v0) - v0 * t0;
                int i1 = lane + 32;
                float t1 = (float)((((i1 < 64 ? bb1 : bb2) >> (i1 & 31))) & 1u);
                cs += softplusf(v1) - v1 * t1;
                int i2 = lane + 64;
                if (i2 < 80) {
                    float t2 = (float)((bb2 >> (i2 & 31)) & 1u);
                    cs += softplusf(v2) - v2 * t2;
                }
            }
            #pragma unroll
            for (int o = 16; o > 0; o >>= 1)
                cs += __shfl_down_sync(0xffffffffu, cs, o);
            float cls_sum = __shfl_sync(0xffffffffu, cs, 0);

            // box/conf channels 0..4 live at i2 = 80..84 → lanes 16..20
            float p0 = __shfl_sync(0xffffffffu, v2, 16);
            float p1 = __shfl_sync(0xffffffffu, v2, 17);
            float p2 = __shfl_sync(0xffffffffu, v2, 18);
            float p3 = __shfl_sync(0xffffffffu, v2, 19);
            float pc = __shfl_sync(0xffffffffu, v2, 20);

            if (lane == 0) {
                float cx = bx * IMG, cy = by * IMG;
                float tw = bz * IMG, th = bw * IMG;
                float pcx = (sigmoidf(p0) + (float)gi) * STRIDEF;
                float pcy = (sigmoidf(p1) + (float)gj) * STRIDEF;
                float pw = anch[2 * a]     * __expf(p2);
                float ph = anch[2 * a + 1] * __expf(p3);

                float ciou = ciou_f(pcx - 0.5f * pw, pcy - 0.5f * ph,
                                    pcx + 0.5f * pw, pcy + 0.5f * ph,
                                    cx - 0.5f * tw, cy - 0.5f * th,
                                    cx + 0.5f * tw, cy + 0.5f * th);
                float sp  = softplusf(pc);
                s_objv[0] = (sp - pc) - ciou;   // bce(conf,1) - ciou
                s_objv[1] = cls_sum;
                s_objv[2] = sp;
            }
        } else {
            if (lane == 0) { s_objv[0] = 0.f; s_objv[1] = 0.f; s_objv[2] = 0.f; }
        }
    }

    // ── all warps: conf softplus chunk (overlaps owner's RT2 latency) ──
    float s = 0.0f;
    #pragma unroll
    for (int k = 0; k < 2; k++) {
        int i = k * NTHR + tid;
        if (i < F4_PER_BLK) {
            int idx = blk * F4_PER_BLK + i;
            int plane = idx / (SSP / 4);
            int off4  = idx - plane * (SSP / 4);
            int bb = plane / AA, aa_ = plane - AA * bb;
            const float4* p4 = (const float4*)(preds +
                ((size_t)(bb * (AA * CH) + aa_ * CH + 4)) * SSP);
            float4 v = p4[off4];
            s += softplusf(v.x) + softplusf(v.y) + softplusf(v.z) + softplusf(v.w);
        }
    }

    // ── all warps: global nobj over their 4 batches (registers only) ──
    unsigned cnt = 0;
    #pragma unroll
    for (int r = 0; r < 4; r++) {
        int cell_r = assign_cell(tb[r], anch);
        unsigned M = __match_any_sync(0xffffffffu, cell_r);
        unsigned lead = __ballot_sync(0xffffffffu, lane == (__ffs(M) - 1));
        cnt += __popc(lead);
    }

    #pragma unroll
    for (int o = 16; o > 0; o >>= 1)
        s += __shfl_down_sync(0xffffffffu, s, o);
    if (lane == 0) { red_conf[w] = s; s_nobj[w] = (float)cnt; }

    __syncthreads();                        // the ONLY block barrier

    if (tid == 0) {
        float conf_sum = red_conf[0] + red_conf[1] + red_conf[2] + red_conf[3];
        float nobj = s_nobj[0] + s_nobj[1] + s_nobj[2] + s_nobj[3];
        float dn_obj   = fmaxf(nobj, 1.0f);
        float dn_noobj = fmaxf((float)CELLS - nobj, 1.0f);
        float dn_cls   = fmaxf(nobj * (float)NC, 1.0f);

        float c = 0.5f * (conf_sum - s_objv[2]) / dn_noobj
                + s_objv[0] / dn_obj
                + s_objv[1] / dn_cls;
        if (blk == 0) c += 1.0f;            // constant term of loss_ciou
        atomicAdd(out, c);                  // RED, fire-and-forget
    }
}

extern "C" void kernel_launch(void* const* d_in, const int* in_sizes, int n_in,
                              void* d_out, int out_size)
{
    const float* preds   = (const float*)d_in[0];
    const float* anchors = (const float*)d_in[1];
    const int*   tcls    = (const int*)d_in[2];
    const float* tbox    = (const float*)d_in[3];

    cudaMemsetAsync(d_out, 0, sizeof(float));
    yolo_one<<<NTARG, NTHR>>>(preds, anchors, tcls, tbox, (float*)d_out);
}

// round 13
// speedup vs baseline: 1.0158x; 1.0158x over previous
#include <cuda_runtime.h>
#include <math.h>

#define BB 16
#define AA 3
#define SDIM 80
#define NC 80
#define NT 32
#define SSP (SDIM * SDIM)             // 6400
#define CH (5 + NC)                   // 85
#define CELLS (BB * AA * SSP)         // 307200
#define NTARG (BB * NT)               // 512 = grid size
#define NTHR 128
#define F4_TOTAL (CELLS / 4)          // 76800
#define F4_PER_BLK (F4_TOTAL / NTARG) // 150
#define EPSF 1e-7f
#define IMG 640.0f
#define STRIDEF 8.0f

__device__ __forceinline__ float softplusf(float x) {
    return fmaxf(x, 0.0f) + __logf(1.0f + __expf(-fabsf(x)));   // arg in [1,2]
}
__device__ __forceinline__ float sigmoidf(float x) {
    return 1.0f / (1.0f + __expf(-x));
}

// fast-div version: used CONSISTENTLY for nobj count and owner dedup so the
// two can never disagree. 2^-21 rel err on the IoU ratio; argmax flip needs a
// ~1e-6 near-tie between anchors.
__device__ __forceinline__ int assign_cell(float4 tb, const float* anch) {
    int gi = min(max((int)floorf(tb.x * (float)SDIM), 0), SDIM - 1);
    int gj = min(max((int)floorf(tb.y * (float)SDIM), 0), SDIM - 1);
    float tw = tb.z * IMG, th = tb.w * IMG;
    float best = -1.0f; int a = 0;
    #pragma unroll
    for (int k = 0; k < AA; k++) {
        float awk = anch[2 * k], ahk = anch[2 * k + 1];
        float inter = fminf(tw, awk) * fminf(th, ahk);
        float un = tw * th + awk * ahk - inter;
        float r = __fdividef(inter, un);
        if (r > best) { best = r; a = k; }    // first-max wins
    }
    return (a * SDIM + gj) * SDIM + gi;
}

__device__ __forceinline__ float ciou_f(
    float px1, float py1, float px2, float py2,
    float tx1, float ty1, float tx2, float ty2)
{
    float iw = fmaxf(fminf(px2, tx2) - fmaxf(px1, tx1), 0.0f);
    float ih = fmaxf(fminf(py2, ty2) - fmaxf(py1, ty1), 0.0f);
    float inter = iw * ih;
    float pa = fmaxf(px2 - px1, 0.0f) * fmaxf(py2 - py1, 0.0f);
    float ta = fmaxf(tx2 - tx1, 0.0f) * fmaxf(ty2 - ty1, 0.0f);
    float un = pa + ta - inter + EPSF;
    float iou = inter / un;
    float dx = 0.5f * (px1 + px2) - 0.5f * (tx1 + tx2);
    float dy = 0.5f * (py1 + py2) - 0.5f * (ty1 + ty2);
    float cd = dx * dx + dy * dy;
    float ew = fmaxf(px2, tx2) - fminf(px1, tx1);
    float eh = fmaxf(py2, ty2) - fminf(py1, ty1);
    float ed = ew * ew + eh * eh + EPSF;
    float pw = fmaxf(px2 - px1, EPSF);
    float ph = fmaxf(py2 - py1, EPSF);
    float tw = fmaxf(tx2 - tx1, EPSF);
    float th = fmaxf(ty2 - ty1, EPSF);
    float da = atanf(tw / th) - atanf(pw / ph);
    float v = (4.0f / ((float)M_PI * (float)M_PI)) * da * da;
    float alpha = v / (1.0f - iou + v + EPSF);
    return iou - cd / ed - alpha * v;
}

__global__ void __launch_bounds__(NTHR)
yolo_one(const float* __restrict__ preds,
         const float* __restrict__ anchors,
         const int* __restrict__ tcls,
         const float* __restrict__ tbox,
         float* __restrict__ out)
{
    __shared__ unsigned s_bits[3];
    __shared__ float    s_objv[3];        // bce-ciou, cls_sum, sp (0 if no owner)
    __shared__ float    red_conf[4];
    __shared__ float    s_nobj[4];

    int tid  = threadIdx.x;
    int lane = tid & 31;
    int w    = tid >> 5;
    int blk  = blockIdx.x;                 // one target per block
    int b = blk >> 5, n = blk & 31;
    int w_own = b >> 2;                    // warp that handles the obj work

    float anch[2 * AA];
    #pragma unroll
    for (int k = 0; k < 2 * AA; k++) anch[k] = anchors[k];

    const float4* tbox4 = (const float4*)tbox;

    // ── RT1 (independent loads, all warps) ──
    float4 tb[4];
    #pragma unroll
    for (int r = 0; r < 4; r++)
        tb[r] = tbox4[(w * 4 + r) * NT + lane];   // warp w: batches 4w..4w+3

    // ── owner warp: dedup + RT2 issue + full obj tail (pre-barrier) ──
    if (w == w_own) {                      // warp-uniform branch
        float4 tbn = tbox4[b * NT + lane]; // batch b, one target per lane
        int    myc = tcls[b * NT + lane];

        int cell_l = assign_cell(tbn, anch);
        unsigned M  = __match_any_sync(0xffffffffu, cell_l);
        unsigned Mn = __shfl_sync(0xffffffffu, M, n);
        int   celln = __shfl_sync(0xffffffffu, cell_l, n);
        bool  owner = ((int)__ffs(Mn) - 1 == n);
        int   lastm = 31 - __clz(Mn);
        float bx = __shfl_sync(0xffffffffu, tbn.x, lastm);
        float by = __shfl_sync(0xffffffffu, tbn.y, lastm);
        float bz = __shfl_sync(0xffffffffu, tbn.z, lastm);
        float bw = __shfl_sync(0xffffffffu, tbn.w, lastm);

        int gi = celln % SDIM;
        int gj = (celln / SDIM) % SDIM;
        int a  = celln / SSP;

        if (owner) {                        // warp-uniform
            size_t base = ((size_t)b * (AA * CH) + (size_t)a * CH) * SSP
                          + (size_t)gj * SDIM + gi;
            float v0 = 0.f, v1 = 0.f, v2 = 0.f;
            {
                int i2 = lane + 64;
                v0 = preds[base + (size_t)(5 + lane) * SSP];
                v1 = preds[base + (size_t)(5 + lane + 32) * SSP];
                if (i2 < 85) {
                    int ch = (i2 < 80) ? (5 + i2) : (i2 - 80);
                    v2 = preds[base + (size_t)ch * SSP];
                }
            }

            if (lane < 3) s_bits[lane] = 0u;
            __syncwarp();
            if ((Mn >> lane) & 1u)
                atomicOr(&s_bits[myc >> 5], 1u << (myc & 31));
            __syncwarp();
            unsigned bb0 = s_bits[0], bb1 = s_bits[1], bb2 = s_bits[2];

            float cs = 0.f;
            {
                int i0 = lane;
                float t0 = (float)((((i0 < 32 ? bb0 : bb1) >> (i0 & 31))) & 1u);
                cs += softplusf(v0) - v0 * t0;
                int i1 = lane + 32;
                float t1 = (float)((((i1 < 64 ? bb1 : bb2) >> (i1 & 31))) & 1u);
                cs += softplusf(v1) - v1 * t1;
                int i2 = lane + 64;
                if (i2 < 80) {
                    float t2 = (float)((bb2 >> (i2 & 31)) & 1u);
                    cs += softplusf(v2) - v2 * t2;
                }
            }
            #pragma unroll
            for (int o = 16; o > 0; o >>= 1)
                cs += __shfl_down_sync(0xffffffffu, cs, o);
            float cls_sum = __shfl_sync(0xffffffffu, cs, 0);

            float p0 = __shfl_sync(0xffffffffu, v2, 16);
            float p1 = __shfl_sync(0xffffffffu, v2, 17);
            float p2 = __shfl_sync(0xffffffffu, v2, 18);
            float p3 = __shfl_sync(0xffffffffu, v2, 19);
            float pc = __shfl_sync(0xffffffffu, v2, 20);

            if (lane == 0) {
                float cx = bx * IMG, cy = by * IMG;
                float tw = bz * IMG, th = bw * IMG;
                float pcx = (sigmoidf(p0) + (float)gi) * STRIDEF;
                float pcy = (sigmoidf(p1) + (float)gj) * STRIDEF;
                float pw = anch[2 * a]     * __expf(p2);
                float ph = anch[2 * a + 1] * __expf(p3);

                float ciou = ciou_f(pcx - 0.5f * pw, pcy - 0.5f * ph,
                                    pcx + 0.5f * pw, pcy + 0.5f * ph,
                                    cx - 0.5f * tw, cy - 0.5f * th,
                                    cx + 0.5f * tw, cy + 0.5f * th);
                float sp  = softplusf(pc);
                s_objv[0] = (sp - pc) - ciou;   // bce(conf,1) - ciou
                s_objv[1] = cls_sum;
                s_objv[2] = sp;
            }
        } else {
            if (lane == 0) { s_objv[0] = 0.f; s_objv[1] = 0.f; s_objv[2] = 0.f; }
        }
    }

    // ── all warps: conf softplus chunk, log-batched:
    //    Σ softplus(x) = Σ max(x,0) + log Π (1 + e^-|x|)   (1 LG2 per thread) ──
    float summax = 0.0f;
    float prod   = 1.0f;
    #pragma unroll
    for (int k = 0; k < 2; k++) {
        int i = k * NTHR + tid;
        if (i < F4_PER_BLK) {
            int idx = blk * F4_PER_BLK + i;
            int plane = idx / (SSP / 4);
            int off4  = idx - plane * (SSP / 4);
            int bb = plane / AA, aa_ = plane - AA * bb;
            const float4* p4 = (const float4*)(preds +
                ((size_t)(bb * (AA * CH) + aa_ * CH + 4)) * SSP);
            float4 v = p4[off4];
            summax += fmaxf(v.x, 0.f) + fmaxf(v.y, 0.f)
                    + fmaxf(v.z, 0.f) + fmaxf(v.w, 0.f);
            prod *= (1.0f + __expf(-fabsf(v.x))) * (1.0f + __expf(-fabsf(v.y)));
            prod *= (1.0f + __expf(-fabsf(v.z))) * (1.0f + __expf(-fabsf(v.w)));
        }
    }
    float s = summax + __logf(prod);      // prod in [1, 256]

    // ── all warps: global nobj over their 4 batches (registers only) ──
    unsigned cnt = 0;
    #pragma unroll
    for (int r = 0; r < 4; r++) {
        int cell_r = assign_cell(tb[r], anch);
        unsigned M = __match_any_sync(0xffffffffu, cell_r);
        unsigned lead = __ballot_sync(0xffffffffu, lane == (__ffs(M) - 1));
        cnt += __popc(lead);
    }

    #pragma unroll
    for (int o = 16; o > 0; o >>= 1)
        s += __shfl_down_sync(0xffffffffu, s, o);
    if (lane == 0) { red_conf[w] = s; s_nobj[w] = (float)cnt; }

    __syncthreads();                        // the ONLY block barrier

    if (tid == 0) {
        float conf_sum = red_conf[0] + red_conf[1] + red_conf[2] + red_conf[3];
        float nobj = s_nobj[0] + s_nobj[1] + s_nobj[2] + s_nobj[3];
        float dn_obj   = fmaxf(nobj, 1.0f);
        float dn_noobj = fmaxf((float)CELLS - nobj, 1.0f);
        float dn_cls   = fmaxf(nobj * (float)NC, 1.0f);

        float c = 0.5f * (conf_sum - s_objv[2]) / dn_noobj
                + s_objv[0] / dn_obj
                + s_objv[1] / dn_cls;
        if (blk == 0) c += 1.0f;            // constant term of loss_ciou
        atomicAdd(out, c);                  // RED, fire-and-forget
    }
}

extern "C" void kernel_launch(void* const* d_in, const int* in_sizes, int n_in,
                              void* d_out, int out_size)
{
    const float* preds   = (const float*)d_in[0];
    const float* anchors = (const float*)d_in[1];
    const int*   tcls    = (const int*)d_in[2];
    const float* tbox    = (const float*)d_in[3];

    cudaMemsetAsync(d_out, 0, sizeof(float));
    yolo_one<<<NTARG, NTHR>>>(preds, anchors, tcls, tbox, (float*)d_out);
}